// round 9
// baseline (speedup 1.0000x reference)
#include <cuda_runtime.h>
#include <cstdint>

// Problem constants
#define N_VOX   262144       // 8 * 32*32*32 voxels
#define KCODES  256
#define EMB     32
#define SPATIAL 32768        // 32*32*32 voxels per batch
#define CH_STRIDE 32768
#define BATCH_STRIDE 1048576 // 32 * 32768
#define OUT_Q_ELEMS 8388608  // 8*32*32768
#define SPAD 36              // padded row stride (floats) for neighbor-sum table

// ---------------- device-global scratch (allocation-free) ----------------
__device__ double g_commit;
__device__ double g_som;
__device__ unsigned long long g_count;
__device__ unsigned int g_ticket;

// ---------------- packed f32x2 helpers ----------------
__device__ __forceinline__ unsigned long long pack2(float lo, float hi) {
    unsigned long long r;
    asm("mov.b64 %0, {%1, %2};" : "=l"(r) : "f"(lo), "f"(hi));
    return r;
}
__device__ __forceinline__ float2 unpack2(unsigned long long v) {
    float lo, hi;
    asm("mov.b64 {%0, %1}, %2;" : "=f"(lo), "=f"(hi) : "l"(v));
    return make_float2(lo, hi);
}
__device__ __forceinline__ unsigned long long fma2(unsigned long long a,
                                                   unsigned long long b,
                                                   unsigned long long c) {
    unsigned long long r;
    asm("fma.rn.f32x2 %0, %1, %2, %3;" : "=l"(r) : "l"(a), "l"(b), "l"(c));
    return r;
}
__device__ __forceinline__ unsigned long long add2(unsigned long long a,
                                                   unsigned long long b) {
    unsigned long long r;
    asm("add.rn.f32x2 %0, %1, %2;" : "=l"(r) : "l"(a), "l"(b));
    return r;
}

// ---------------- single fused kernel ----------------
// Dynamic shared layout (bytes):
//   sW    [256*32] f32 : 0      (32768)  codebook, k-major
//   sS    [256*36] f32 : 32768  (36864)  neighbor-summed codebook, padded
//   sWsq  [256]    f32 : 69632  (1024)   ||w_k||^2
//   sSwsq [256]    f32 : 70656  (1024)   sum of ||w||^2 over N(k) incl self
//   sBest [512]    i32 : 71680  (2048)
//   sRed  [24]     f32 : 73728  (96)
#define SMEM_BYTES 73824

__global__ __launch_bounds__(256, 3) void som_main_kernel(
    const float* __restrict__ x,
    const float* __restrict__ Wc,
    float* __restrict__ outq,
    float* __restrict__ enc,
    float* __restrict__ loss_out)
{
    extern __shared__ __align__(16) char dyn[];
    float* sW    = (float*)(dyn);
    float* sS    = (float*)(dyn + 32768);
    float* sWsq  = (float*)(dyn + 69632);
    float* sSwsq = (float*)(dyn + 70656);
    int*   sBest = (int*)  (dyn + 71680);
    float* sRed  = (float*)(dyn + 73728);

    const int t = threadIdx.x;

    // ---- prologue 1: coop load codebook + row sq-norms via shuffles ----
    {
        const float4* Wv  = (const float4*)Wc;
        float4*       sWv = (float4*)sW;
#pragma unroll
        for (int i = 0; i < 8; i++) {
            float4 v = Wv[t + 256 * i];
            sWv[t + 256 * i] = v;
            float ps = v.x * v.x + v.y * v.y + v.z * v.z + v.w * v.w;
            // 8 consecutive lanes own one 32-float row
            ps += __shfl_xor_sync(0xffffffffu, ps, 1);
            ps += __shfl_xor_sync(0xffffffffu, ps, 2);
            ps += __shfl_xor_sync(0xffffffffu, ps, 4);
            if ((t & 7) == 0) sWsq[(t + 256 * i) >> 3] = ps;
        }
    }
    __syncthreads();

    // ---- prologue 2: neighbor-sum table, column-parallel (conflict-free) ----
    {
#pragma unroll 4
        for (int i = 0; i < 32; i++) {
            const int k = (t >> 5) + 8 * i;     // uniform per warp
            const int c = t & 31;               // lane = column
            float s = sW[k * 32 + c];
            if (k >= 16)        s += sW[(k - 16) * 32 + c];
            if (k < 240)        s += sW[(k + 16) * 32 + c];
            if ((k & 15) != 0)  s += sW[(k - 1) * 32 + c];
            if ((k & 15) != 15) s += sW[(k + 1) * 32 + c];
            sS[k * SPAD + c] = s;
            if (c == 0) {
                float q = sWsq[k];
                if (k >= 16)        q += sWsq[k - 16];
                if (k < 240)        q += sWsq[k + 16];
                if ((k & 15) != 0)  q += sWsq[k - 1];
                if ((k & 15) != 15) q += sWsq[k + 1];
                sSwsq[k] = q;
            }
        }
    }
    __syncthreads();

    // ---- load two x rows (voxels A = base, B = base+256) ----
    const int base = blockIdx.x * 512 + t;      // block covers 512 voxels, same batch
    const int b  = base >> 15;
    const int sp = base & (SPATIAL - 1);
    const float* xpA = x + (size_t)b * BATCH_STRIDE + sp;
    const float* xpB = xpA + 256;

    unsigned long long xrA[16], xrB[16];
    float xsqA = 0.f, xsqB = 0.f;
#pragma unroll
    for (int c = 0; c < EMB; c += 2) {
        float a0 = xpA[(size_t)c * CH_STRIDE];
        float b0 = xpB[(size_t)c * CH_STRIDE];
        float a1 = xpA[(size_t)(c + 1) * CH_STRIDE];
        float b1 = xpB[(size_t)(c + 1) * CH_STRIDE];
        xrA[c >> 1] = pack2(a0, a1);
        xrB[c >> 1] = pack2(b0, b1);
        xsqA += a0 * a0 + a1 * a1;
        xsqB += b0 * b0 + b1 * b1;
    }

    // ---- scan 256 codes: argmax of score = dot - 0.5*||w||^2  ----
    // (argmin dist == argmax score; strict > keeps first index on ties,
    //  matching jnp.argmin first-min semantics)
    float scA = -3.402823466e38f, scB = -3.402823466e38f;
    int   bkA = 0, bkB = 0;
#pragma unroll 2
    for (int k = 0; k < KCODES; k++) {
        const ulonglong2* wr = (const ulonglong2*)(sW + k * 32);
        unsigned long long a0 = 0ull, a1 = 0ull, c0 = 0ull, c1 = 0ull;
#pragma unroll
        for (int i = 0; i < 8; i++) {
            ulonglong2 wv = wr[i];           // 16B stage, consumed immediately
            a0 = fma2(xrA[2 * i],     wv.x, a0);
            c0 = fma2(xrB[2 * i],     wv.x, c0);
            a1 = fma2(xrA[2 * i + 1], wv.y, a1);
            c1 = fma2(xrB[2 * i + 1], wv.y, c1);
        }
        const float hw = sWsq[k];
        {
            float2 s = unpack2(add2(a0, a1));
            float score = fmaf(-0.5f, hw, s.x + s.y);
            if (score > scA) { scA = score; bkA = k; }
        }
        {
            float2 s = unpack2(add2(c0, c1));
            float score = fmaf(-0.5f, hw, s.x + s.y);
            if (score > scB) { scB = score; bkB = k; }
        }
    }

    // recover best distances:  dist* = xsq - 2*score*
    const float bestA = fmaf(-2.f, scA, xsqA);
    const float bestB = fmaf(-2.f, scB, xsqB);

    sBest[t]       = bkA;
    sBest[t + 256] = bkB;

    // ---- quantized outputs (straight-through == W[bestk]) ----
    {
        float* opA = outq + (size_t)b * BATCH_STRIDE + sp;
        float* opB = opA + 256;
        const float4* gwA = (const float4*)(Wc + bkA * EMB);
        const float4* gwB = (const float4*)(Wc + bkB * EMB);
#pragma unroll
        for (int i = 0; i < 8; i++) {
            float4 va = gwA[i];
            float4 vb = gwB[i];
            opA[(size_t)(4 * i + 0) * CH_STRIDE] = va.x;
            opA[(size_t)(4 * i + 1) * CH_STRIDE] = va.y;
            opA[(size_t)(4 * i + 2) * CH_STRIDE] = va.z;
            opA[(size_t)(4 * i + 3) * CH_STRIDE] = va.w;
            opB[(size_t)(4 * i + 0) * CH_STRIDE] = vb.x;
            opB[(size_t)(4 * i + 1) * CH_STRIDE] = vb.y;
            opB[(size_t)(4 * i + 2) * CH_STRIDE] = vb.z;
            opB[(size_t)(4 * i + 3) * CH_STRIDE] = vb.w;
        }
    }

    // ---- somloss via neighbor-aggregate:  cnt*xsq + sum(wsq) - 2*x.S[k*] ----
    float somA, somB;
    int cntA, cntB;
    {
        const ulonglong2* sr = (const ulonglong2*)(sS + bkA * SPAD);
        unsigned long long d0 = 0ull, d1 = 0ull;
#pragma unroll
        for (int i = 0; i < 8; i++) {
            ulonglong2 wv = sr[i];
            d0 = fma2(xrA[2 * i],     wv.x, d0);
            d1 = fma2(xrA[2 * i + 1], wv.y, d1);
        }
        float2 s = unpack2(add2(d0, d1));
        cntA = 1 + (bkA >= 16) + (bkA < 240) + ((bkA & 15) != 0) + ((bkA & 15) != 15);
        somA = fmaf(-2.f, s.x + s.y, fmaf((float)cntA, xsqA, sSwsq[bkA]));
    }
    {
        const ulonglong2* sr = (const ulonglong2*)(sS + bkB * SPAD);
        unsigned long long d0 = 0ull, d1 = 0ull;
#pragma unroll
        for (int i = 0; i < 8; i++) {
            ulonglong2 wv = sr[i];
            d0 = fma2(xrB[2 * i],     wv.x, d0);
            d1 = fma2(xrB[2 * i + 1], wv.y, d1);
        }
        float2 s = unpack2(add2(d0, d1));
        cntB = 1 + (bkB >= 16) + (bkB < 240) + ((bkB & 15) != 0) + ((bkB & 15) != 15);
        somB = fmaf(-2.f, s.x + s.y, fmaf((float)cntB, xsqB, sSwsq[bkB]));
    }

    // ---- block reduction -> double atomics ----
    float cs = bestA + bestB;
    float ss = somA + somB;
    float ns = (float)(cntA + cntB);
#pragma unroll
    for (int o = 16; o > 0; o >>= 1) {
        cs += __shfl_down_sync(0xffffffffu, cs, o);
        ss += __shfl_down_sync(0xffffffffu, ss, o);
        ns += __shfl_down_sync(0xffffffffu, ns, o);
    }
    const int wid = t >> 5, lid = t & 31;
    if (lid == 0) { sRed[wid] = cs; sRed[8 + wid] = ss; sRed[16 + wid] = ns; }
    __syncthreads();   // covers sBest for enc epilogue AND sRed for t0
    if (t == 0) {
        float c = 0.f, s2 = 0.f, nn = 0.f;
#pragma unroll
        for (int i = 0; i < 8; i++) { c += sRed[i]; s2 += sRed[8 + i]; nn += sRed[16 + i]; }
        atomicAdd(&g_commit, (double)c);
        atomicAdd(&g_som,    (double)s2);
        atomicAdd(&g_count,  (unsigned long long)(nn + 0.5f));
    }

    // ---- one-hot encodings: block's own 512x256 tile, coalesced ----
    {
        float* encBlock = enc + (size_t)blockIdx.x * (512 * KCODES);
#pragma unroll 8
        for (int r = 0; r < 512; r++) {
            encBlock[(size_t)r * KCODES + t] = (sBest[r] == t) ? 1.0f : 0.0f;
        }
    }

    // ---- last block computes the loss scalar and resets accumulators ----
    __threadfence();
    __shared__ unsigned int sLast;
    if (t == 0) sLast = atomicAdd(&g_ticket, 1u);
    __syncthreads();
    if (sLast == gridDim.x - 1 && t == 0) {
        double c = atomicAdd(&g_commit, 0.0);
        double s = atomicAdd(&g_som, 0.0);
        unsigned long long n = atomicAdd(&g_count, 0ull);
        loss_out[0] = (float)(6.0 * (c / (double)OUT_Q_ELEMS) + s / (double)n);
        g_commit = 0.0;
        g_som    = 0.0;
        g_count  = 0ull;
        __threadfence();
        atomicExch(&g_ticket, 0u);
    }
}

// ---------------- launch ----------------
extern "C" void kernel_launch(void* const* d_in, const int* in_sizes, int n_in,
                              void* d_out, int out_size)
{
    const float* x  = (const float*)d_in[0];   // [8,32,32,32,32] f32
    const float* Wc = (const float*)d_in[1];   // [256,32] f32
    float* out = (float*)d_out;

    float* loss_ptr = out;                      // 1 element
    float* outq     = out + 1;                  // 8388608 elements
    float* enc      = out + 1 + OUT_Q_ELEMS;    // 67108864 elements

    cudaFuncSetAttribute(som_main_kernel,
                         cudaFuncAttributeMaxDynamicSharedMemorySize, SMEM_BYTES);
    som_main_kernel<<<N_VOX / 512, 256, SMEM_BYTES>>>(x, Wc, outq, enc, loss_ptr);
}

// round 10
// speedup vs baseline: 1.2416x; 1.2416x over previous
#include <cuda_runtime.h>
#include <cstdint>

// Problem constants
#define N_VOX   262144       // 8 * 32*32*32 voxels
#define KCODES  256
#define EMB     32
#define SPATIAL 32768        // 32*32*32 voxels per batch
#define CH_STRIDE 32768
#define BATCH_STRIDE 1048576 // 32 * 32768
#define OUT_Q_ELEMS 8388608  // 8*32*32768
#define SPAD 36              // padded row stride (floats) for neighbor-sum table

// ---------------- device-global scratch (allocation-free) ----------------
__device__ double g_commit;
__device__ double g_som;
__device__ unsigned long long g_count;
__device__ unsigned int g_ticket;

// ---------------- packed f32x2 helpers ----------------
__device__ __forceinline__ unsigned long long pack2(float lo, float hi) {
    unsigned long long r;
    asm("mov.b64 %0, {%1, %2};" : "=l"(r) : "f"(lo), "f"(hi));
    return r;
}
__device__ __forceinline__ float2 unpack2(unsigned long long v) {
    float lo, hi;
    asm("mov.b64 {%0, %1}, %2;" : "=f"(lo), "=f"(hi) : "l"(v));
    return make_float2(lo, hi);
}
__device__ __forceinline__ unsigned long long fma2(unsigned long long a,
                                                   unsigned long long b,
                                                   unsigned long long c) {
    unsigned long long r;
    asm("fma.rn.f32x2 %0, %1, %2, %3;" : "=l"(r) : "l"(a), "l"(b), "l"(c));
    return r;
}
__device__ __forceinline__ unsigned long long add2(unsigned long long a,
                                                   unsigned long long b) {
    unsigned long long r;
    asm("add.rn.f32x2 %0, %1, %2;" : "=l"(r) : "l"(a), "l"(b));
    return r;
}

// ---------------- single fused kernel ----------------
// Dynamic shared layout (bytes):
//   sW    [256*32] f32 : 0      (32768)  codebook, k-major
//   sS    [256*36] f32 : 32768  (36864)  neighbor-summed codebook, padded
//   sWsq  [256]    f32 : 69632  (1024)   ||w_k||^2
//   sSwsq [256]    f32 : 70656  (1024)   sum of ||w||^2 over N(k) incl self
//   sBest [512]    i32 : 71680  (2048)
//   sRed  [24]     f32 : 73728  (96)
//   sHalf [256]    u64 : 73824  (2048)   packed (-0.5*||w_k||^2, 0)
#define SMEM_BYTES 75872

__global__ __launch_bounds__(256, 2) void som_main_kernel(
    const float* __restrict__ x,
    const float* __restrict__ Wc,
    float* __restrict__ outq,
    float* __restrict__ enc,
    float* __restrict__ loss_out)
{
    extern __shared__ __align__(16) char dyn[];
    float* sW    = (float*)(dyn);
    float* sS    = (float*)(dyn + 32768);
    float* sWsq  = (float*)(dyn + 69632);
    float* sSwsq = (float*)(dyn + 70656);
    int*   sBest = (int*)  (dyn + 71680);
    float* sRed  = (float*)(dyn + 73728);
    unsigned long long* sHalf = (unsigned long long*)(dyn + 73824);

    const int t = threadIdx.x;

    // ---- prologue 1: coop load codebook + row sq-norms via shuffles ----
    {
        const float4* Wv  = (const float4*)Wc;
        float4*       sWv = (float4*)sW;
#pragma unroll
        for (int i = 0; i < 8; i++) {
            float4 v = Wv[t + 256 * i];
            sWv[t + 256 * i] = v;
            float ps = v.x * v.x + v.y * v.y + v.z * v.z + v.w * v.w;
            // 8 consecutive lanes own one 32-float row
            ps += __shfl_xor_sync(0xffffffffu, ps, 1);
            ps += __shfl_xor_sync(0xffffffffu, ps, 2);
            ps += __shfl_xor_sync(0xffffffffu, ps, 4);
            if ((t & 7) == 0) sWsq[(t + 256 * i) >> 3] = ps;
        }
    }
    __syncthreads();

    // ---- prologue 2: neighbor-sum table + packed -wsq/2 table ----
    sHalf[t] = pack2(-0.5f * sWsq[t], 0.f);
    {
#pragma unroll 4
        for (int i = 0; i < 32; i++) {
            const int k = (t >> 5) + 8 * i;     // uniform per warp
            const int c = t & 31;               // lane = column
            float s = sW[k * 32 + c];
            if (k >= 16)        s += sW[(k - 16) * 32 + c];
            if (k < 240)        s += sW[(k + 16) * 32 + c];
            if ((k & 15) != 0)  s += sW[(k - 1) * 32 + c];
            if ((k & 15) != 15) s += sW[(k + 1) * 32 + c];
            sS[k * SPAD + c] = s;
            if (c == 0) {
                float q = sWsq[k];
                if (k >= 16)        q += sWsq[k - 16];
                if (k < 240)        q += sWsq[k + 16];
                if ((k & 15) != 0)  q += sWsq[k - 1];
                if ((k & 15) != 15) q += sWsq[k + 1];
                sSwsq[k] = q;
            }
        }
    }
    __syncthreads();

    // ---- load two x rows (voxels A = base, B = base+256) ----
    const int base = blockIdx.x * 512 + t;      // block covers 512 voxels, same batch
    const int b  = base >> 15;
    const int sp = base & (SPATIAL - 1);
    const float* xpA = x + (size_t)b * BATCH_STRIDE + sp;
    const float* xpB = xpA + 256;

    unsigned long long xrA[16], xrB[16];
    float xsqA = 0.f, xsqB = 0.f;
#pragma unroll
    for (int c = 0; c < EMB; c += 2) {
        float a0 = xpA[(size_t)c * CH_STRIDE];
        float b0 = xpB[(size_t)c * CH_STRIDE];
        float a1 = xpA[(size_t)(c + 1) * CH_STRIDE];
        float b1 = xpB[(size_t)(c + 1) * CH_STRIDE];
        xrA[c >> 1] = pack2(a0, a1);
        xrB[c >> 1] = pack2(b0, b1);
        xsqA += a0 * a0 + a1 * a1;
        xsqB += b0 * b0 + b1 * b1;
    }

    // ---- scan 256 codes: argmax of score = dot - 0.5*||w||^2 ----
    // -wsq/2 pre-folded into the first fma's addend (off the dependent tail).
    // strict > keeps first index on ties == jnp.argmin first-min semantics.
    float scA = -3.402823466e38f, scB = -3.402823466e38f;
    int   bkA = 0, bkB = 0;
#pragma unroll 4
    for (int k = 0; k < KCODES; k++) {
        const ulonglong2* wr = (const ulonglong2*)(sW + k * 32);
        const unsigned long long h = sHalf[k];   // packed (-wsq/2, 0)
        unsigned long long a0 = h, a1 = 0ull, c0 = h, c1 = 0ull;
#pragma unroll
        for (int i = 0; i < 8; i++) {
            ulonglong2 wv = wr[i];
            a0 = fma2(xrA[2 * i],     wv.x, a0);
            c0 = fma2(xrB[2 * i],     wv.x, c0);
            a1 = fma2(xrA[2 * i + 1], wv.y, a1);
            c1 = fma2(xrB[2 * i + 1], wv.y, c1);
        }
        {
            float2 s = unpack2(add2(a0, a1));
            float score = s.x + s.y;
            if (score > scA) { scA = score; bkA = k; }
        }
        {
            float2 s = unpack2(add2(c0, c1));
            float score = s.x + s.y;
            if (score > scB) { scB = score; bkB = k; }
        }
    }

    // recover best distances:  dist* = xsq - 2*score*   (score has -wsq/2 folded)
    const float bestA = fmaf(-2.f, scA, xsqA);
    const float bestB = fmaf(-2.f, scB, xsqB);

    sBest[t]       = bkA;
    sBest[t + 256] = bkB;

    // ---- quantized outputs (straight-through == W[bestk]) ----
    {
        float* opA = outq + (size_t)b * BATCH_STRIDE + sp;
        float* opB = opA + 256;
        const float4* gwA = (const float4*)(Wc + bkA * EMB);
        const float4* gwB = (const float4*)(Wc + bkB * EMB);
#pragma unroll
        for (int i = 0; i < 8; i++) {
            float4 va = gwA[i];
            float4 vb = gwB[i];
            opA[(size_t)(4 * i + 0) * CH_STRIDE] = va.x;
            opA[(size_t)(4 * i + 1) * CH_STRIDE] = va.y;
            opA[(size_t)(4 * i + 2) * CH_STRIDE] = va.z;
            opA[(size_t)(4 * i + 3) * CH_STRIDE] = va.w;
            opB[(size_t)(4 * i + 0) * CH_STRIDE] = vb.x;
            opB[(size_t)(4 * i + 1) * CH_STRIDE] = vb.y;
            opB[(size_t)(4 * i + 2) * CH_STRIDE] = vb.z;
            opB[(size_t)(4 * i + 3) * CH_STRIDE] = vb.w;
        }
    }

    // ---- somloss via neighbor-aggregate:  cnt*xsq + sum(wsq) - 2*x.S[k*] ----
    float somA, somB;
    int cntA, cntB;
    {
        const ulonglong2* sr = (const ulonglong2*)(sS + bkA * SPAD);
        unsigned long long d0 = 0ull, d1 = 0ull;
#pragma unroll
        for (int i = 0; i < 8; i++) {
            ulonglong2 wv = sr[i];
            d0 = fma2(xrA[2 * i],     wv.x, d0);
            d1 = fma2(xrA[2 * i + 1], wv.y, d1);
        }
        float2 s = unpack2(add2(d0, d1));
        cntA = 1 + (bkA >= 16) + (bkA < 240) + ((bkA & 15) != 0) + ((bkA & 15) != 15);
        somA = fmaf(-2.f, s.x + s.y, fmaf((float)cntA, xsqA, sSwsq[bkA]));
    }
    {
        const ulonglong2* sr = (const ulonglong2*)(sS + bkB * SPAD);
        unsigned long long d0 = 0ull, d1 = 0ull;
#pragma unroll
        for (int i = 0; i < 8; i++) {
            ulonglong2 wv = sr[i];
            d0 = fma2(xrB[2 * i],     wv.x, d0);
            d1 = fma2(xrB[2 * i + 1], wv.y, d1);
        }
        float2 s = unpack2(add2(d0, d1));
        cntB = 1 + (bkB >= 16) + (bkB < 240) + ((bkB & 15) != 0) + ((bkB & 15) != 15);
        somB = fmaf(-2.f, s.x + s.y, fmaf((float)cntB, xsqB, sSwsq[bkB]));
    }

    // ---- block reduction -> double atomics ----
    float cs = bestA + bestB;
    float ss = somA + somB;
    float ns = (float)(cntA + cntB);
#pragma unroll
    for (int o = 16; o > 0; o >>= 1) {
        cs += __shfl_down_sync(0xffffffffu, cs, o);
        ss += __shfl_down_sync(0xffffffffu, ss, o);
        ns += __shfl_down_sync(0xffffffffu, ns, o);
    }
    const int wid = t >> 5, lid = t & 31;
    if (lid == 0) { sRed[wid] = cs; sRed[8 + wid] = ss; sRed[16 + wid] = ns; }
    __syncthreads();   // covers sBest for enc epilogue AND sRed for t0
    if (t == 0) {
        float c = 0.f, s2 = 0.f, nn = 0.f;
#pragma unroll
        for (int i = 0; i < 8; i++) { c += sRed[i]; s2 += sRed[8 + i]; nn += sRed[16 + i]; }
        atomicAdd(&g_commit, (double)c);
        atomicAdd(&g_som,    (double)s2);
        atomicAdd(&g_count,  (unsigned long long)(nn + 0.5f));
    }

    // ---- one-hot encodings: block's own 512x256 tile, coalesced ----
    {
        float* encBlock = enc + (size_t)blockIdx.x * (512 * KCODES);
#pragma unroll 8
        for (int r = 0; r < 512; r++) {
            encBlock[(size_t)r * KCODES + t] = (sBest[r] == t) ? 1.0f : 0.0f;
        }
    }

    // ---- last block computes the loss scalar and resets accumulators ----
    __threadfence();
    __shared__ unsigned int sLast;
    if (t == 0) sLast = atomicAdd(&g_ticket, 1u);
    __syncthreads();
    if (sLast == gridDim.x - 1 && t == 0) {
        double c = atomicAdd(&g_commit, 0.0);
        double s = atomicAdd(&g_som, 0.0);
        unsigned long long n = atomicAdd(&g_count, 0ull);
        loss_out[0] = (float)(6.0 * (c / (double)OUT_Q_ELEMS) + s / (double)n);
        g_commit = 0.0;
        g_som    = 0.0;
        g_count  = 0ull;
        __threadfence();
        atomicExch(&g_ticket, 0u);
    }
}

// ---------------- launch ----------------
extern "C" void kernel_launch(void* const* d_in, const int* in_sizes, int n_in,
                              void* d_out, int out_size)
{
    const float* x  = (const float*)d_in[0];   // [8,32,32,32,32] f32
    const float* Wc = (const float*)d_in[1];   // [256,32] f32
    float* out = (float*)d_out;

    float* loss_ptr = out;                      // 1 element
    float* outq     = out + 1;                  // 8388608 elements
    float* enc      = out + 1 + OUT_Q_ELEMS;    // 67108864 elements

    cudaFuncSetAttribute(som_main_kernel,
                         cudaFuncAttributeMaxDynamicSharedMemorySize, SMEM_BYTES);
    som_main_kernel<<<N_VOX / 512, 256, SMEM_BYTES>>>(x, Wc, outq, enc, loss_ptr);
}

// round 11
// speedup vs baseline: 1.3368x; 1.0767x over previous
#include <cuda_runtime.h>
#include <cstdint>

// Problem constants
#define N_VOX   262144       // 8 * 32*32*32 voxels
#define KCODES  256
#define EMB     32
#define SPATIAL 32768        // 32*32*32 voxels per batch
#define CH_STRIDE 32768
#define BATCH_STRIDE 1048576 // 32 * 32768
#define OUT_Q_ELEMS 8388608  // 8*32*32768
#define SPAD 36              // padded row stride (floats) for neighbor-sum table
#define NTILES 512           // 512-voxel tiles
#define GRID 296             // 2 blocks/SM * 148 SMs, persistent

// ---------------- device-global scratch (allocation-free) ----------------
__device__ double g_commit;
__device__ double g_som;
__device__ unsigned long long g_count;
__device__ unsigned int g_ticket;

// ---------------- packed f32x2 helpers ----------------
__device__ __forceinline__ unsigned long long pack2(float lo, float hi) {
    unsigned long long r;
    asm("mov.b64 %0, {%1, %2};" : "=l"(r) : "f"(lo), "f"(hi));
    return r;
}
__device__ __forceinline__ float2 unpack2(unsigned long long v) {
    float lo, hi;
    asm("mov.b64 {%0, %1}, %2;" : "=f"(lo), "=f"(hi) : "l"(v));
    return make_float2(lo, hi);
}
__device__ __forceinline__ unsigned long long fma2(unsigned long long a,
                                                   unsigned long long b,
                                                   unsigned long long c) {
    unsigned long long r;
    asm("fma.rn.f32x2 %0, %1, %2, %3;" : "=l"(r) : "l"(a), "l"(b), "l"(c));
    return r;
}
__device__ __forceinline__ unsigned long long add2(unsigned long long a,
                                                   unsigned long long b) {
    unsigned long long r;
    asm("add.rn.f32x2 %0, %1, %2;" : "=l"(r) : "l"(a), "l"(b));
    return r;
}

// ---------------- single fused persistent kernel ----------------
// Dynamic shared layout (bytes):
//   sW    [256*32] f32 : 0      (32768)  codebook, k-major
//   sS    [256*36] f32 : 32768  (36864)  neighbor-summed codebook, padded
//   sWsq  [256]    f32 : 69632  (1024)   ||w_k||^2
//   sSwsq [256]    f32 : 70656  (1024)   sum of ||w||^2 over N(k) incl self
//   sBest [512]    i32 : 71680  (2048)
//   sRed  [24]     f32 : 73728  (96)
#define SMEM_BYTES 73824

__global__ __launch_bounds__(256, 2) void som_main_kernel(
    const float* __restrict__ x,
    const float* __restrict__ Wc,
    float* __restrict__ outq,
    float* __restrict__ enc,
    float* __restrict__ loss_out)
{
    extern __shared__ __align__(16) char dyn[];
    float* sW    = (float*)(dyn);
    float* sS    = (float*)(dyn + 32768);
    float* sWsq  = (float*)(dyn + 69632);
    float* sSwsq = (float*)(dyn + 70656);
    int*   sBest = (int*)  (dyn + 71680);
    float* sRed  = (float*)(dyn + 73728);

    const int t = threadIdx.x;

    // ---- prologue (once per persistent block) ----
    {
        const float4* Wv  = (const float4*)Wc;
        float4*       sWv = (float4*)sW;
#pragma unroll
        for (int i = 0; i < 8; i++) {
            float4 v = Wv[t + 256 * i];
            sWv[t + 256 * i] = v;
            float ps = v.x * v.x + v.y * v.y + v.z * v.z + v.w * v.w;
            ps += __shfl_xor_sync(0xffffffffu, ps, 1);
            ps += __shfl_xor_sync(0xffffffffu, ps, 2);
            ps += __shfl_xor_sync(0xffffffffu, ps, 4);
            if ((t & 7) == 0) sWsq[(t + 256 * i) >> 3] = ps;
        }
    }
    __syncthreads();
    {
#pragma unroll 4
        for (int i = 0; i < 32; i++) {
            const int k = (t >> 5) + 8 * i;     // uniform per warp
            const int c = t & 31;               // lane = column
            float s = sW[k * 32 + c];
            if (k >= 16)        s += sW[(k - 16) * 32 + c];
            if (k < 240)        s += sW[(k + 16) * 32 + c];
            if ((k & 15) != 0)  s += sW[(k - 1) * 32 + c];
            if ((k & 15) != 15) s += sW[(k + 1) * 32 + c];
            sS[k * SPAD + c] = s;
            if (c == 0) {
                float q = sWsq[k];
                if (k >= 16)        q += sWsq[k - 16];
                if (k < 240)        q += sWsq[k + 16];
                if ((k & 15) != 0)  q += sWsq[k - 1];
                if ((k & 15) != 15) q += sWsq[k + 1];
                sSwsq[k] = q;
            }
        }
    }
    __syncthreads();

    float csAcc = 0.f, ssAcc = 0.f, nsAcc = 0.f;   // per-thread running loss sums

    // ---- persistent tile loop ----
    for (int tl = blockIdx.x; tl < NTILES; tl += GRID) {
        const int base = tl * 512 + t;
        const int b  = base >> 15;
        const int sp = base & (SPATIAL - 1);
        const float* xpA = x + (size_t)b * BATCH_STRIDE + sp;
        const float* xpB = xpA + 256;

        unsigned long long xrA[16], xrB[16];
        float xsqA = 0.f, xsqB = 0.f;
#pragma unroll
        for (int c = 0; c < EMB; c += 2) {
            float a0 = xpA[(size_t)c * CH_STRIDE];
            float b0 = xpB[(size_t)c * CH_STRIDE];
            float a1 = xpA[(size_t)(c + 1) * CH_STRIDE];
            float b1 = xpB[(size_t)(c + 1) * CH_STRIDE];
            xrA[c >> 1] = pack2(a0, a1);
            xrB[c >> 1] = pack2(b0, b1);
            xsqA += a0 * a0 + a1 * a1;
            xsqB += b0 * b0 + b1 * b1;
        }

        // ---- pipelined scan: argmax of score = dot - 0.5*||w||^2 ----
        // W row (128B) consumed as two 64B halves, double-buffered so the
        // 4 LDS.128 of one half fly under the 16 FFMA2 of the other.
        float scA = -3.402823466e38f, scB = -3.402823466e38f;
        int   bkA = 0, bkB = 0;
        const ulonglong2* wr = (const ulonglong2*)sW;   // 8 u2 per row
        ulonglong2 p0 = wr[0], p1 = wr[1], p2 = wr[2], p3 = wr[3];
        for (int k = 0; k < KCODES; k++) {
            const float wsq = sWsq[k];
            // stage half1 of row k
            ulonglong2 q0 = wr[k * 8 + 4], q1 = wr[k * 8 + 5],
                       q2 = wr[k * 8 + 6], q3 = wr[k * 8 + 7];
            // consume half0 (p) with xr[0..7]
            unsigned long long a0, a1, c0, c1;
            a0 = fma2(xrA[0], p0.x, 0ull);  c0 = fma2(xrB[0], p0.x, 0ull);
            a1 = fma2(xrA[1], p0.y, 0ull);  c1 = fma2(xrB[1], p0.y, 0ull);
            a0 = fma2(xrA[2], p1.x, a0);    c0 = fma2(xrB[2], p1.x, c0);
            a1 = fma2(xrA[3], p1.y, a1);    c1 = fma2(xrB[3], p1.y, c1);
            a0 = fma2(xrA[4], p2.x, a0);    c0 = fma2(xrB[4], p2.x, c0);
            a1 = fma2(xrA[5], p2.y, a1);    c1 = fma2(xrB[5], p2.y, c1);
            a0 = fma2(xrA[6], p3.x, a0);    c0 = fma2(xrB[6], p3.x, c0);
            a1 = fma2(xrA[7], p3.y, a1);    c1 = fma2(xrB[7], p3.y, c1);
            // stage half0 of row k+1 (at k=255 over-reads into sS: valid smem,
            // never consumed)
            p0 = wr[k * 8 + 8];  p1 = wr[k * 8 + 9];
            p2 = wr[k * 8 + 10]; p3 = wr[k * 8 + 11];
            // consume half1 (q) with xr[8..15]
            a0 = fma2(xrA[8],  q0.x, a0);   c0 = fma2(xrB[8],  q0.x, c0);
            a1 = fma2(xrA[9],  q0.y, a1);   c1 = fma2(xrB[9],  q0.y, c1);
            a0 = fma2(xrA[10], q1.x, a0);   c0 = fma2(xrB[10], q1.x, c0);
            a1 = fma2(xrA[11], q1.y, a1);   c1 = fma2(xrB[11], q1.y, c1);
            a0 = fma2(xrA[12], q2.x, a0);   c0 = fma2(xrB[12], q2.x, c0);
            a1 = fma2(xrA[13], q2.y, a1);   c1 = fma2(xrB[13], q2.y, c1);
            a0 = fma2(xrA[14], q3.x, a0);   c0 = fma2(xrB[14], q3.x, c0);
            a1 = fma2(xrA[15], q3.y, a1);   c1 = fma2(xrB[15], q3.y, c1);
            // tail (strict > keeps first index == jnp.argmin first-min)
            {
                float2 s = unpack2(add2(a0, a1));
                float score = fmaf(-0.5f, wsq, s.x + s.y);
                if (score > scA) { scA = score; bkA = k; }
            }
            {
                float2 s = unpack2(add2(c0, c1));
                float score = fmaf(-0.5f, wsq, s.x + s.y);
                if (score > scB) { scB = score; bkB = k; }
            }
        }

        // dist* = xsq - 2*score*
        const float bestA = fmaf(-2.f, scA, xsqA);
        const float bestB = fmaf(-2.f, scB, xsqB);

        sBest[t]       = bkA;
        sBest[t + 256] = bkB;

        // ---- quantized outputs (straight-through == W[bestk]) ----
        {
            float* opA = outq + (size_t)b * BATCH_STRIDE + sp;
            float* opB = opA + 256;
            const float4* gwA = (const float4*)(Wc + bkA * EMB);
            const float4* gwB = (const float4*)(Wc + bkB * EMB);
#pragma unroll
            for (int i = 0; i < 8; i++) {
                float4 va = gwA[i];
                float4 vb = gwB[i];
                opA[(size_t)(4 * i + 0) * CH_STRIDE] = va.x;
                opA[(size_t)(4 * i + 1) * CH_STRIDE] = va.y;
                opA[(size_t)(4 * i + 2) * CH_STRIDE] = va.z;
                opA[(size_t)(4 * i + 3) * CH_STRIDE] = va.w;
                opB[(size_t)(4 * i + 0) * CH_STRIDE] = vb.x;
                opB[(size_t)(4 * i + 1) * CH_STRIDE] = vb.y;
                opB[(size_t)(4 * i + 2) * CH_STRIDE] = vb.z;
                opB[(size_t)(4 * i + 3) * CH_STRIDE] = vb.w;
            }
        }

        // ---- somloss: cnt*xsq + sum(wsq over N(k*)) - 2*x.S[k*] ----
        {
            const ulonglong2* sr = (const ulonglong2*)(sS + bkA * SPAD);
            unsigned long long d0 = 0ull, d1 = 0ull;
#pragma unroll
            for (int i = 0; i < 8; i++) {
                ulonglong2 wv = sr[i];
                d0 = fma2(xrA[2 * i],     wv.x, d0);
                d1 = fma2(xrA[2 * i + 1], wv.y, d1);
            }
            float2 s = unpack2(add2(d0, d1));
            int cntA = 1 + (bkA >= 16) + (bkA < 240) + ((bkA & 15) != 0) + ((bkA & 15) != 15);
            ssAcc += fmaf(-2.f, s.x + s.y, fmaf((float)cntA, xsqA, sSwsq[bkA]));
            nsAcc += (float)cntA;
        }
        {
            const ulonglong2* sr = (const ulonglong2*)(sS + bkB * SPAD);
            unsigned long long d0 = 0ull, d1 = 0ull;
#pragma unroll
            for (int i = 0; i < 8; i++) {
                ulonglong2 wv = sr[i];
                d0 = fma2(xrB[2 * i],     wv.x, d0);
                d1 = fma2(xrB[2 * i + 1], wv.y, d1);
            }
            float2 s = unpack2(add2(d0, d1));
            int cntB = 1 + (bkB >= 16) + (bkB < 240) + ((bkB & 15) != 0) + ((bkB & 15) != 15);
            ssAcc += fmaf(-2.f, s.x + s.y, fmaf((float)cntB, xsqB, sSwsq[bkB]));
            nsAcc += (float)cntB;
        }
        csAcc += bestA + bestB;

        // ---- one-hot encodings: this tile's 512x256 block, coalesced ----
        __syncthreads();   // sBest fully written
        {
            float* encBlock = enc + (size_t)tl * (512 * KCODES);
#pragma unroll 8
            for (int r = 0; r < 512; r++) {
                encBlock[(size_t)r * KCODES + t] = (sBest[r] == t) ? 1.0f : 0.0f;
            }
        }
        __syncthreads();   // sBest consumed before next tile overwrites
    }

    // ---- one block-level reduction + atomics per persistent block ----
#pragma unroll
    for (int o = 16; o > 0; o >>= 1) {
        csAcc += __shfl_down_sync(0xffffffffu, csAcc, o);
        ssAcc += __shfl_down_sync(0xffffffffu, ssAcc, o);
        nsAcc += __shfl_down_sync(0xffffffffu, nsAcc, o);
    }
    const int wid = t >> 5, lid = t & 31;
    if (lid == 0) { sRed[wid] = csAcc; sRed[8 + wid] = ssAcc; sRed[16 + wid] = nsAcc; }
    __syncthreads();
    if (t == 0) {
        float c = 0.f, s2 = 0.f, nn = 0.f;
#pragma unroll
        for (int i = 0; i < 8; i++) { c += sRed[i]; s2 += sRed[8 + i]; nn += sRed[16 + i]; }
        atomicAdd(&g_commit, (double)c);
        atomicAdd(&g_som,    (double)s2);
        atomicAdd(&g_count,  (unsigned long long)(nn + 0.5f));
    }

    // ---- last block computes the loss scalar and resets accumulators ----
    __threadfence();
    __shared__ unsigned int sLast;
    if (t == 0) sLast = atomicAdd(&g_ticket, 1u);
    __syncthreads();
    if (sLast == gridDim.x - 1 && t == 0) {
        double c = atomicAdd(&g_commit, 0.0);
        double s = atomicAdd(&g_som, 0.0);
        unsigned long long n = atomicAdd(&g_count, 0ull);
        loss_out[0] = (float)(6.0 * (c / (double)OUT_Q_ELEMS) + s / (double)n);
        g_commit = 0.0;
        g_som    = 0.0;
        g_count  = 0ull;
        __threadfence();
        atomicExch(&g_ticket, 0u);
    }
}

// ---------------- launch ----------------
extern "C" void kernel_launch(void* const* d_in, const int* in_sizes, int n_in,
                              void* d_out, int out_size)
{
    const float* x  = (const float*)d_in[0];   // [8,32,32,32,32] f32
    const float* Wc = (const float*)d_in[1];   // [256,32] f32
    float* out = (float*)d_out;

    float* loss_ptr = out;                      // 1 element
    float* outq     = out + 1;                  // 8388608 elements
    float* enc      = out + 1 + OUT_Q_ELEMS;    // 67108864 elements

    cudaFuncSetAttribute(som_main_kernel,
                         cudaFuncAttributeMaxDynamicSharedMemorySize, SMEM_BYTES);
    som_main_kernel<<<GRID, 256, SMEM_BYTES>>>(x, Wc, outq, enc, loss_ptr);
}

// round 13
// speedup vs baseline: 1.5086x; 1.1285x over previous
#include <cuda_runtime.h>
#include <cstdint>

// Problem constants
#define KCODES  256
#define EMB     32
#define SPATIAL 32768
#define CH_STRIDE 32768
#define BATCH_STRIDE 1048576
#define OUT_Q_ELEMS 8388608
#define SPAD 36
#define TILE_M 256           // voxels per tile (16 warps x 16 rows)
#define NTILES 1024
#define GRID 148
#define APAD 33              // A staging row stride (floats)

// dynamic smem layout (bytes)
#define OFF_A1     0         // A split-hi [256][33] f32
#define OFF_A2     33792     // A split-lo [256][33] f32
#define OFF_BF     67584     // B fragments uint4[32 nt][4 ks][32 lane]
#define OFF_BIAS   133120    // float2[32 nt][4 tg]
#define OFF_SS     134144    // neighbor-sum table f32 [256][36]
#define OFF_SSWSQ  171008    // f32 [256]
#define OFF_SWSQ   172032    // f32 [256]
#define OFF_SBEST  173056    // i32 [256]
#define OFF_SSCORE 174080    // f32 [256]
#define OFF_SRED   175104    // f32 [48]
#define SMEM_BYTES 175296

// ---------------- device-global scratch ----------------
__device__ double g_commit;
__device__ double g_som;
__device__ unsigned long long g_count;
__device__ unsigned int g_ticket;

// ---------------- tf32 helpers ----------------
__device__ __forceinline__ uint32_t f2tf32(float v) {
    uint32_t u;
    asm("cvt.rna.tf32.f32 %0, %1;" : "=r"(u) : "f"(v));
    return u;
}
__device__ __forceinline__ void tf32split(float v, uint32_t& hi, uint32_t& lo) {
    hi = f2tf32(v);
    lo = f2tf32(v - __uint_as_float(hi));
}
__device__ __forceinline__ void mma1688(float& c0, float& c1, float& c2, float& c3,
                                        uint32_t a0, uint32_t a1, uint32_t a2, uint32_t a3,
                                        uint32_t b0, uint32_t b1) {
    asm volatile(
        "mma.sync.aligned.m16n8k8.row.col.f32.tf32.tf32.f32 "
        "{%0,%1,%2,%3}, {%4,%5,%6,%7}, {%8,%9}, {%0,%1,%2,%3};"
        : "+f"(c0), "+f"(c1), "+f"(c2), "+f"(c3)
        : "r"(a0), "r"(a1), "r"(a2), "r"(a3), "r"(b0), "r"(b1));
}

// ---------------- single fused persistent kernel ----------------
__global__ void __launch_bounds__(512, 1)
som_mma_kernel(const float* __restrict__ x,
               const float* __restrict__ Wc,
               float* __restrict__ outq,
               float* __restrict__ enc,
               float* __restrict__ loss_out)
{
    extern __shared__ __align__(16) char dyn[];
    uint32_t* A1p   = (uint32_t*)(dyn + OFF_A1);
    uint32_t* A2p   = (uint32_t*)(dyn + OFF_A2);
    uint4*    BF    = (uint4*)   (dyn + OFF_BF);
    float2*   BIAS  = (float2*)  (dyn + OFF_BIAS);
    float*    sS    = (float*)   (dyn + OFF_SS);
    float*    sSwsq = (float*)   (dyn + OFF_SSWSQ);
    float*    sWsq  = (float*)   (dyn + OFF_SWSQ);
    int*      sBest = (int*)     (dyn + OFF_SBEST);
    float*    sScore= (float*)   (dyn + OFF_SSCORE);
    float*    sRed  = (float*)   (dyn + OFF_SRED);

    const int t   = threadIdx.x;
    const int wid = t >> 5;
    const int lid = t & 31;
    const int g   = lid >> 2;      // groupID
    const int tg  = lid & 3;       // threadID_in_group

    // ---- prologue A: ||w_k||^2 (one row per thread, t<256) ----
    if (t < KCODES) {
        const float* wrow = Wc + t * EMB;
        float q = 0.f;
#pragma unroll
        for (int c = 0; c < EMB; c++) { float v = wrow[c]; q += v * v; }
        sWsq[t] = q;
    }

    // ---- prologue B: B fragment table (tf32 hi/lo pairs, fragment order) ----
    // entry idx: lane=idx&31, ks=(idx>>5)&3, nt=idx>>7
    {
#pragma unroll
        for (int i = 0; i < 8; i++) {
            const int idx = t + 512 * i;
            const int ln = idx & 31, ks = (idx >> 5) & 3, nt = idx >> 7;
            const int gg = ln >> 2, tt = ln & 3;
            const int code = nt * 8 + gg;
            const int k0 = ks * 8 + tt;
            float w0 = Wc[code * EMB + k0];
            float w1 = Wc[code * EMB + k0 + 4];
            uint32_t h0, l0, h1, l1;
            tf32split(w0, h0, l0);
            tf32split(w1, h1, l1);
            BF[idx] = make_uint4(h0, h1, l0, l1);
        }
    }

    // ---- prologue C: neighbor-sum table (coalesced from global W) ----
    {
#pragma unroll
        for (int i = 0; i < 16; i++) {
            const int idx = t + 512 * i;
            const int k = idx >> 5;      // uniform per warp
            const int c = idx & 31;      // lane = column
            float s = Wc[k * EMB + c];
            if (k >= 16)        s += Wc[(k - 16) * EMB + c];
            if (k < 240)        s += Wc[(k + 16) * EMB + c];
            if ((k & 15) != 0)  s += Wc[(k - 1) * EMB + c];
            if ((k & 15) != 15) s += Wc[(k + 1) * EMB + c];
            sS[k * SPAD + c] = s;
        }
    }
    __syncthreads();

    // ---- prologue D: bias table + neighbor wsq sums ----
    if (t < 128) {                       // [nt 0..31][tg 0..3]
        const int nt = t >> 2, tt = t & 3;
        BIAS[nt * 4 + tt] = make_float2(-0.5f * sWsq[nt * 8 + 2 * tt],
                                        -0.5f * sWsq[nt * 8 + 2 * tt + 1]);
    }
    if (t < KCODES) {
        const int k = t;
        float q = sWsq[k];
        if (k >= 16)        q += sWsq[k - 16];
        if (k < 240)        q += sWsq[k + 16];
        if ((k & 15) != 0)  q += sWsq[k - 1];
        if ((k & 15) != 15) q += sWsq[k + 1];
        sSwsq[k] = q;
    }
    __syncthreads();

    float csAcc = 0.f, ssAcc = 0.f, nsAcc = 0.f;

    // ---- persistent tile loop: 256 voxels per tile ----
    for (int tl = blockIdx.x; tl < NTILES; tl += GRID) {
        const int b   = tl >> 7;
        const int sp0 = (tl & 127) << 8;
        const float* xbase = x + (size_t)b * BATCH_STRIDE + sp0;

        // stage A splits: 256 voxels x 32 channels (coalesced LDG)
#pragma unroll
        for (int i = 0; i < 16; i++) {
            const int idx = t + 512 * i;
            const int c = idx >> 8, v = idx & 255;
            float val = xbase[(size_t)c * CH_STRIDE + v];
            uint32_t hi, lo;
            tf32split(val, hi, lo);
            A1p[v * APAD + c] = hi;
            A2p[v * APAD + c] = lo;
        }
        __syncthreads();

        // load A fragments for this warp's 16 rows (held across the n-sweep)
        const int rA = (wid << 4) + g;        // row g of this warp tile
        uint32_t a1f[4][4], a2f[4][4];
#pragma unroll
        for (int ks = 0; ks < 4; ks++) {
            const int cc = ks * 8 + tg;
            a1f[ks][0] = A1p[rA * APAD + cc];
            a1f[ks][1] = A1p[(rA + 8) * APAD + cc];
            a1f[ks][2] = A1p[rA * APAD + cc + 4];
            a1f[ks][3] = A1p[(rA + 8) * APAD + cc + 4];
            a2f[ks][0] = A2p[rA * APAD + cc];
            a2f[ks][1] = A2p[(rA + 8) * APAD + cc];
            a2f[ks][2] = A2p[rA * APAD + cc + 4];
            a2f[ks][3] = A2p[(rA + 8) * APAD + cc + 4];
        }

        // ---- scan 32 n-tiles: score = x.w - 0.5*||w||^2 (3xTF32) ----
        float bs0 = -3.402823466e38f, bs1 = -3.402823466e38f;
        int   bk0 = 0, bk1 = 0;
#pragma unroll 2
        for (int nt = 0; nt < 32; nt++) {
            const float2 bias = BIAS[nt * 4 + tg];   // broadcast across g
            // 3 independent term accumulators (hi*hi gets the bias)
            float u0 = bias.x, u1 = bias.y, u2 = bias.x, u3 = bias.y;
            float v0 = 0.f, v1 = 0.f, v2 = 0.f, v3 = 0.f;
            float w0 = 0.f, w1 = 0.f, w2 = 0.f, w3 = 0.f;
            const uint4* bfp = BF + nt * 128 + lid;
#pragma unroll
            for (int ks = 0; ks < 4; ks++) {
                const uint4 bb = bfp[ks * 32];
                mma1688(u0, u1, u2, u3, a1f[ks][0], a1f[ks][1], a1f[ks][2], a1f[ks][3], bb.x, bb.y);
                mma1688(v0, v1, v2, v3, a1f[ks][0], a1f[ks][1], a1f[ks][2], a1f[ks][3], bb.z, bb.w);
                mma1688(w0, w1, w2, w3, a2f[ks][0], a2f[ks][1], a2f[ks][2], a2f[ks][3], bb.x, bb.y);
            }
            const float c0 = u0 + v0 + w0;   // row rA,   col n0
            const float c1 = u1 + v1 + w1;   // row rA,   col n0+1
            const float c2 = u2 + v2 + w2;   // row rA+8, col n0
            const float c3 = u3 + v3 + w3;   // row rA+8, col n0+1
            const int n0 = nt * 8 + 2 * tg;
            if (c0 > bs0) { bs0 = c0; bk0 = n0; }
            if (c1 > bs0) { bs0 = c1; bk0 = n0 + 1; }
            if (c2 > bs1) { bs1 = c2; bk1 = n0; }
            if (c3 > bs1) { bs1 = c3; bk1 = n0 + 1; }
        }

        // cross-lane reduce within the 4-lane group (tie -> smaller k)
#pragma unroll
        for (int off = 1; off <= 2; off <<= 1) {
            float os0 = __shfl_xor_sync(0xffffffffu, bs0, off);
            int   ok0 = __shfl_xor_sync(0xffffffffu, bk0, off);
            float os1 = __shfl_xor_sync(0xffffffffu, bs1, off);
            int   ok1 = __shfl_xor_sync(0xffffffffu, bk1, off);
            if (os0 > bs0 || (os0 == bs0 && ok0 < bk0)) { bs0 = os0; bk0 = ok0; }
            if (os1 > bs1 || (os1 == bs1 && ok1 < bk1)) { bs1 = os1; bk1 = ok1; }
        }
        if (tg == 0) {
            sBest[rA] = bk0;      sScore[rA] = bs0;
            sBest[rA + 8] = bk1;  sScore[rA + 8] = bs1;
        }
        __syncthreads();

        // ---- epilogue: warps 0-7 per-voxel, warps 8-15 one-hot enc ----
        if (t < TILE_M) {
            const int v = t;
            const int bkv = sBest[v];
            const float mysc = sScore[v];
            float xsq = 0.f, somdot = 0.f;
            const float*  xv = xbase + v;
            float*        ov = outq + (size_t)b * BATCH_STRIDE + sp0 + v;
            const float4* gw = (const float4*)(Wc + bkv * EMB);
            const float*  sr = sS + bkv * SPAD;
#pragma unroll
            for (int c4 = 0; c4 < 8; c4++) {
                float4 wv = gw[c4];
                float x0 = xv[(size_t)(4 * c4 + 0) * CH_STRIDE];
                float x1 = xv[(size_t)(4 * c4 + 1) * CH_STRIDE];
                float x2 = xv[(size_t)(4 * c4 + 2) * CH_STRIDE];
                float x3 = xv[(size_t)(4 * c4 + 3) * CH_STRIDE];
                xsq += x0 * x0 + x1 * x1 + x2 * x2 + x3 * x3;
                somdot += x0 * sr[4 * c4 + 0] + x1 * sr[4 * c4 + 1]
                        + x2 * sr[4 * c4 + 2] + x3 * sr[4 * c4 + 3];
                ov[(size_t)(4 * c4 + 0) * CH_STRIDE] = wv.x;
                ov[(size_t)(4 * c4 + 1) * CH_STRIDE] = wv.y;
                ov[(size_t)(4 * c4 + 2) * CH_STRIDE] = wv.z;
                ov[(size_t)(4 * c4 + 3) * CH_STRIDE] = wv.w;
            }
            const int cnt = 1 + (bkv >= 16) + (bkv < 240)
                          + ((bkv & 15) != 0) + ((bkv & 15) != 15);
            csAcc += fmaf(-2.f, mysc, xsq);   // dist* = xsq - 2*score*
            ssAcc += fmaf(-2.f, somdot, fmaf((float)cnt, xsq, sSwsq[bkv]));
            nsAcc += (float)cnt;
        } else {
            const int w8 = wid - 8;
            float* encT = enc + (size_t)tl * (TILE_M * KCODES);
#pragma unroll 4
            for (int r0 = 0; r0 < 32; r0++) {
                const int r = (w8 << 5) + r0;
                const int kb = sBest[r];
                float* er = encT + (size_t)r * KCODES;
#pragma unroll
                for (int gq = 0; gq < 8; gq++) {
                    const int c = lid + (gq << 5);
                    er[c] = (c == kb) ? 1.0f : 0.0f;
                }
            }
        }
        __syncthreads();   // sBest/sScore consumed before next tile
    }

    // ---- block reduction -> double atomics ----
#pragma unroll
    for (int o = 16; o > 0; o >>= 1) {
        csAcc += __shfl_down_sync(0xffffffffu, csAcc, o);
        ssAcc += __shfl_down_sync(0xffffffffu, ssAcc, o);
        nsAcc += __shfl_down_sync(0xffffffffu, nsAcc, o);
    }
    if (lid == 0) { sRed[wid] = csAcc; sRed[16 + wid] = ssAcc; sRed[32 + wid] = nsAcc; }
    __syncthreads();
    if (t == 0) {
        float c = 0.f, s2 = 0.f, nn = 0.f;
#pragma unroll
        for (int i = 0; i < 16; i++) { c += sRed[i]; s2 += sRed[16 + i]; nn += sRed[32 + i]; }
        atomicAdd(&g_commit, (double)c);
        atomicAdd(&g_som,    (double)s2);
        atomicAdd(&g_count,  (unsigned long long)(nn + 0.5f));
    }

    // ---- last block: loss scalar + accumulator reset ----
    __threadfence();
    __shared__ unsigned int sLast;
    if (t == 0) sLast = atomicAdd(&g_ticket, 1u);
    __syncthreads();
    if (sLast == gridDim.x - 1 && t == 0) {
        double c = atomicAdd(&g_commit, 0.0);
        double s = atomicAdd(&g_som, 0.0);
        unsigned long long n = atomicAdd(&g_count, 0ull);
        loss_out[0] = (float)(6.0 * (c / (double)OUT_Q_ELEMS) + s / (double)n);
        g_commit = 0.0;
        g_som    = 0.0;
        g_count  = 0ull;
        __threadfence();
        atomicExch(&g_ticket, 0u);
    }
}

// ---------------- launch ----------------
extern "C" void kernel_launch(void* const* d_in, const int* in_sizes, int n_in,
                              void* d_out, int out_size)
{
    const float* x  = (const float*)d_in[0];   // [8,32,32,32,32] f32
    const float* Wc = (const float*)d_in[1];   // [256,32] f32
    float* out = (float*)d_out;

    float* loss_ptr = out;                      // 1 element
    float* outq     = out + 1;                  // 8388608 elements
    float* enc      = out + 1 + OUT_Q_ELEMS;    // 67108864 elements

    cudaFuncSetAttribute(som_mma_kernel,
                         cudaFuncAttributeMaxDynamicSharedMemorySize, SMEM_BYTES);
    som_mma_kernel<<<GRID, 512, SMEM_BYTES>>>(x, Wc, outq, enc, loss_ptr);
}

// round 14
// speedup vs baseline: 1.6302x; 1.0806x over previous
#include <cuda_runtime.h>
#include <cstdint>

// Problem constants
#define KCODES  256
#define EMB     32
#define SPATIAL 32768
#define CH_STRIDE 32768
#define BATCH_STRIDE 1048576
#define OUT_Q_ELEMS 8388608
#define SPAD 36
#define TILE_M 256           // voxels per tile (16 warps x 16 rows)
#define NTILES 1024
#define GRID 148
#define APAD 33              // A staging row stride (floats)

// dynamic smem layout (bytes)
#define OFF_A0     0         // A raw fp32 buffer 0: [256][33]
#define OFF_A1     33792     // A raw fp32 buffer 1
#define OFF_BF     67584     // B fragments uint4[32 nt][4 ks][32 lane]
#define OFF_BIAS   133120    // float2[32 nt][4 tg]
#define OFF_SS     134144    // neighbor-sum table f32 [256][36]
#define OFF_SSWSQ  171008    // f32 [256]
#define OFF_SWSQ   172032    // f32 [256]
#define OFF_SBEST  173056    // i32 [256]
#define OFF_SSCORE 174080    // f32 [256]
#define OFF_SRED   175104    // f32 [48]
#define SMEM_BYTES 175296

// ---------------- device-global scratch ----------------
__device__ double g_commit;
__device__ double g_som;
__device__ unsigned long long g_count;
__device__ unsigned int g_ticket;

// ---------------- helpers ----------------
__device__ __forceinline__ uint32_t smem_u32(const void* p) {
    uint32_t a;
    asm("{ .reg .u64 t; cvta.to.shared.u64 t, %1; cvt.u32.u64 %0, t; }"
        : "=r"(a) : "l"(p));
    return a;
}
__device__ __forceinline__ uint32_t f2tf32(float v) {
    uint32_t u;
    asm("cvt.rna.tf32.f32 %0, %1;" : "=r"(u) : "f"(v));
    return u;
}
__device__ __forceinline__ void tf32split(float v, uint32_t& hi, uint32_t& lo) {
    hi = f2tf32(v);
    lo = f2tf32(v - __uint_as_float(hi));
}
__device__ __forceinline__ void mma1688(float& c0, float& c1, float& c2, float& c3,
                                        uint32_t a0, uint32_t a1, uint32_t a2, uint32_t a3,
                                        uint32_t b0, uint32_t b1) {
    asm volatile(
        "mma.sync.aligned.m16n8k8.row.col.f32.tf32.tf32.f32 "
        "{%0,%1,%2,%3}, {%4,%5,%6,%7}, {%8,%9}, {%0,%1,%2,%3};"
        : "+f"(c0), "+f"(c1), "+f"(c2), "+f"(c3)
        : "r"(a0), "r"(a1), "r"(a2), "r"(a3), "r"(b0), "r"(b1));
}
__device__ __forceinline__ void cp4(uint32_t dst, const float* src) {
    asm volatile("cp.async.ca.shared.global [%0], [%1], 4;"
                 :: "r"(dst), "l"(src));
}
#define CP_COMMIT() asm volatile("cp.async.commit_group;" ::: "memory")
#define CP_WAIT_ALL() asm volatile("cp.async.wait_group 0;" ::: "memory")

// ---------------- single fused persistent kernel ----------------
__global__ void __launch_bounds__(512, 1)
som_mma_kernel(const float* __restrict__ x,
               const float* __restrict__ Wc,
               float* __restrict__ outq,
               float* __restrict__ enc,
               float* __restrict__ loss_out)
{
    extern __shared__ __align__(16) char dyn[];
    uint4*    BF    = (uint4*)   (dyn + OFF_BF);
    float2*   BIAS  = (float2*)  (dyn + OFF_BIAS);
    float*    sS    = (float*)   (dyn + OFF_SS);
    float*    sSwsq = (float*)   (dyn + OFF_SSWSQ);
    float*    sWsq  = (float*)   (dyn + OFF_SWSQ);
    int*      sBest = (int*)     (dyn + OFF_SBEST);
    float*    sScore= (float*)   (dyn + OFF_SSCORE);
    float*    sRed  = (float*)   (dyn + OFF_SRED);

    const int t   = threadIdx.x;
    const int wid = t >> 5;
    const int lid = t & 31;
    const int g   = lid >> 2;      // groupID
    const int tg  = lid & 3;       // threadID_in_group
    const uint32_t smem_base = smem_u32(dyn);

    // ---- prologue A: ||w_k||^2 ----
    if (t < KCODES) {
        const float* wrow = Wc + t * EMB;
        float q = 0.f;
#pragma unroll
        for (int c = 0; c < EMB; c++) { float v = wrow[c]; q += v * v; }
        sWsq[t] = q;
    }

    // ---- prologue B: B fragment table (tf32 hi/lo pairs, fragment order) ----
    {
#pragma unroll
        for (int i = 0; i < 8; i++) {
            const int idx = t + 512 * i;
            const int ln = idx & 31, ks = (idx >> 5) & 3, nt = idx >> 7;
            const int gg = ln >> 2, tt = ln & 3;
            const int code = nt * 8 + gg;
            const int k0 = ks * 8 + tt;
            float w0 = Wc[code * EMB + k0];
            float w1 = Wc[code * EMB + k0 + 4];
            uint32_t h0, l0, h1, l1;
            tf32split(w0, h0, l0);
            tf32split(w1, h1, l1);
            BF[idx] = make_uint4(h0, h1, l0, l1);
        }
    }

    // ---- prologue C: neighbor-sum table ----
    {
#pragma unroll
        for (int i = 0; i < 16; i++) {
            const int idx = t + 512 * i;
            const int k = idx >> 5;      // uniform per warp
            const int c = idx & 31;      // lane = column
            float s = Wc[k * EMB + c];
            if (k >= 16)        s += Wc[(k - 16) * EMB + c];
            if (k < 240)        s += Wc[(k + 16) * EMB + c];
            if ((k & 15) != 0)  s += Wc[(k - 1) * EMB + c];
            if ((k & 15) != 15) s += Wc[(k + 1) * EMB + c];
            sS[k * SPAD + c] = s;
        }
    }
    __syncthreads();

    // ---- prologue D: bias table + neighbor wsq sums ----
    if (t < 128) {
        const int nt = t >> 2, tt = t & 3;
        BIAS[nt * 4 + tt] = make_float2(-0.5f * sWsq[nt * 8 + 2 * tt],
                                        -0.5f * sWsq[nt * 8 + 2 * tt + 1]);
    }
    if (t < KCODES) {
        const int k = t;
        float q = sWsq[k];
        if (k >= 16)        q += sWsq[k - 16];
        if (k < 240)        q += sWsq[k + 16];
        if ((k & 15) != 0)  q += sWsq[k - 1];
        if ((k & 15) != 15) q += sWsq[k + 1];
        sSwsq[k] = q;
    }
    __syncthreads();

    float csAcc = 0.f, ssAcc = 0.f, nsAcc = 0.f;

    // ---- cp.async staging of one tile's x into a raw A buffer ----
    auto stage_tile = [&](int tile, uint32_t bufOff) {
        const int bb = tile >> 7;
        const int ss = (tile & 127) << 8;
        const float* xb = x + (size_t)bb * BATCH_STRIDE + ss;
        const uint32_t dstBase = smem_base + bufOff;
#pragma unroll
        for (int i = 0; i < 16; i++) {
            const int idx = t + 512 * i;
            const int c = idx >> 8, v = idx & 255;
            cp4(dstBase + (uint32_t)(v * APAD + c) * 4,
                xb + (size_t)c * CH_STRIDE + v);
        }
    };

    // prefetch first tile
    int pbuf = 0;
    if (blockIdx.x < NTILES) stage_tile(blockIdx.x, OFF_A0);
    CP_COMMIT();

    // ---- persistent tile loop: 256 voxels per tile ----
    for (int tl = blockIdx.x; tl < NTILES; tl += GRID) {
        const int b   = tl >> 7;
        const int sp0 = (tl & 127) << 8;

        CP_WAIT_ALL();          // current tile staged (overlapped prior iter)
        __syncthreads();        // visible to all; prior-iter readers done

        const uint32_t curOff = pbuf ? OFF_A1 : OFF_A0;
        float* Araw = (float*)(dyn + curOff);

        // kick prefetch of the next tile into the other buffer
        if (tl + GRID < NTILES) stage_tile(tl + GRID, pbuf ? OFF_A0 : OFF_A1);
        CP_COMMIT();
        pbuf ^= 1;

        // load + split A fragments for this warp's 16 rows
        const int rA = (wid << 4) + g;
        uint32_t a1f[4][4], a2f[4][4];
#pragma unroll
        for (int ks = 0; ks < 4; ks++) {
            const int cc = ks * 8 + tg;
            float f0 = Araw[rA * APAD + cc];
            float f1 = Araw[(rA + 8) * APAD + cc];
            float f2 = Araw[rA * APAD + cc + 4];
            float f3 = Araw[(rA + 8) * APAD + cc + 4];
            tf32split(f0, a1f[ks][0], a2f[ks][0]);
            tf32split(f1, a1f[ks][1], a2f[ks][1]);
            tf32split(f2, a1f[ks][2], a2f[ks][2]);
            tf32split(f3, a1f[ks][3], a2f[ks][3]);
        }

        // ---- scan 32 n-tiles: score = x.w - 0.5*||w||^2 (3xTF32) ----
        float bs0 = -3.402823466e38f, bs1 = -3.402823466e38f;
        int   bk0 = 0, bk1 = 0;
#pragma unroll 2
        for (int nt = 0; nt < 32; nt++) {
            const float2 bias = BIAS[nt * 4 + tg];
            float u0 = bias.x, u1 = bias.y, u2 = bias.x, u3 = bias.y;
            float v0 = 0.f, v1 = 0.f, v2 = 0.f, v3 = 0.f;
            float w0 = 0.f, w1 = 0.f, w2 = 0.f, w3 = 0.f;
            const uint4* bfp = BF + nt * 128 + lid;
#pragma unroll
            for (int ks = 0; ks < 4; ks++) {
                const uint4 bb = bfp[ks * 32];
                mma1688(u0, u1, u2, u3, a1f[ks][0], a1f[ks][1], a1f[ks][2], a1f[ks][3], bb.x, bb.y);
                mma1688(v0, v1, v2, v3, a1f[ks][0], a1f[ks][1], a1f[ks][2], a1f[ks][3], bb.z, bb.w);
                mma1688(w0, w1, w2, w3, a2f[ks][0], a2f[ks][1], a2f[ks][2], a2f[ks][3], bb.x, bb.y);
            }
            const float c0 = u0 + v0 + w0;
            const float c1 = u1 + v1 + w1;
            const float c2 = u2 + v2 + w2;
            const float c3 = u3 + v3 + w3;
            const int n0 = nt * 8 + 2 * tg;
            if (c0 > bs0) { bs0 = c0; bk0 = n0; }
            if (c1 > bs0) { bs0 = c1; bk0 = n0 + 1; }
            if (c2 > bs1) { bs1 = c2; bk1 = n0; }
            if (c3 > bs1) { bs1 = c3; bk1 = n0 + 1; }
        }

        // cross-lane reduce within the 4-lane group (tie -> smaller k)
#pragma unroll
        for (int off = 1; off <= 2; off <<= 1) {
            float os0 = __shfl_xor_sync(0xffffffffu, bs0, off);
            int   ok0 = __shfl_xor_sync(0xffffffffu, bk0, off);
            float os1 = __shfl_xor_sync(0xffffffffu, bs1, off);
            int   ok1 = __shfl_xor_sync(0xffffffffu, bk1, off);
            if (os0 > bs0 || (os0 == bs0 && ok0 < bk0)) { bs0 = os0; bk0 = ok0; }
            if (os1 > bs1 || (os1 == bs1 && ok1 < bk1)) { bs1 = os1; bk1 = ok1; }
        }
        if (tg == 0) {
            sBest[rA] = bk0;      sScore[rA] = bs0;
            sBest[rA + 8] = bk1;  sScore[rA + 8] = bs1;
        }
        __syncthreads();

        // ---- epilogue: warps 0-7 per-voxel, warps 8-15 one-hot enc ----
        if (t < TILE_M) {
            const int v = t;
            const int bkv = sBest[v];
            const float mysc = sScore[v];
            float xsq = 0.f, somdot = 0.f;
            const float*  av = Araw + v * APAD;    // x row from smem (conflict-free)
            float*        ov = outq + (size_t)b * BATCH_STRIDE + sp0 + v;
            const float4* gw = (const float4*)(Wc + bkv * EMB);
            const float*  sr = sS + bkv * SPAD;
#pragma unroll
            for (int c4 = 0; c4 < 8; c4++) {
                float4 wv = gw[c4];
                float x0 = av[4 * c4 + 0];
                float x1 = av[4 * c4 + 1];
                float x2 = av[4 * c4 + 2];
                float x3 = av[4 * c4 + 3];
                xsq += x0 * x0 + x1 * x1 + x2 * x2 + x3 * x3;
                somdot += x0 * sr[4 * c4 + 0] + x1 * sr[4 * c4 + 1]
                        + x2 * sr[4 * c4 + 2] + x3 * sr[4 * c4 + 3];
                ov[(size_t)(4 * c4 + 0) * CH_STRIDE] = wv.x;
                ov[(size_t)(4 * c4 + 1) * CH_STRIDE] = wv.y;
                ov[(size_t)(4 * c4 + 2) * CH_STRIDE] = wv.z;
                ov[(size_t)(4 * c4 + 3) * CH_STRIDE] = wv.w;
            }
            const int cnt = 1 + (bkv >= 16) + (bkv < 240)
                          + ((bkv & 15) != 0) + ((bkv & 15) != 15);
            csAcc += fmaf(-2.f, mysc, xsq);   // dist* = xsq - 2*score*
            ssAcc += fmaf(-2.f, somdot, fmaf((float)cnt, xsq, sSwsq[bkv]));
            nsAcc += (float)cnt;
        } else {
            const int w8 = wid - 8;
            float* encT = enc + (size_t)tl * (TILE_M * KCODES);
#pragma unroll 4
            for (int r0 = 0; r0 < 32; r0++) {
                const int r = (w8 << 5) + r0;
                const int kb = sBest[r];
                float* er = encT + (size_t)r * KCODES;
#pragma unroll
                for (int gq = 0; gq < 8; gq++) {
                    const int c = lid + (gq << 5);
                    er[c] = (c == kb) ? 1.0f : 0.0f;
                }
            }
        }
        // no tail sync: top-of-loop CP_WAIT_ALL + __syncthreads covers reuse
    }

    // ---- block reduction -> double atomics ----
#pragma unroll
    for (int o = 16; o > 0; o >>= 1) {
        csAcc += __shfl_down_sync(0xffffffffu, csAcc, o);
        ssAcc += __shfl_down_sync(0xffffffffu, ssAcc, o);
        nsAcc += __shfl_down_sync(0xffffffffu, nsAcc, o);
    }
    if (lid == 0) { sRed[wid] = csAcc; sRed[16 + wid] = ssAcc; sRed[32 + wid] = nsAcc; }
    __syncthreads();
    if (t == 0) {
        float c = 0.f, s2 = 0.f, nn = 0.f;
#pragma unroll
        for (int i = 0; i < 16; i++) { c += sRed[i]; s2 += sRed[16 + i]; nn += sRed[32 + i]; }
        atomicAdd(&g_commit, (double)c);
        atomicAdd(&g_som,    (double)s2);
        atomicAdd(&g_count,  (unsigned long long)(nn + 0.5f));
    }

    // ---- last block: loss scalar + accumulator reset ----
    __threadfence();
    __shared__ unsigned int sLast;
    if (t == 0) sLast = atomicAdd(&g_ticket, 1u);
    __syncthreads();
    if (sLast == gridDim.x - 1 && t == 0) {
        double c = atomicAdd(&g_commit, 0.0);
        double s = atomicAdd(&g_som, 0.0);
        unsigned long long n = atomicAdd(&g_count, 0ull);
        loss_out[0] = (float)(6.0 * (c / (double)OUT_Q_ELEMS) + s / (double)n);
        g_commit = 0.0;
        g_som    = 0.0;
        g_count  = 0ull;
        __threadfence();
        atomicExch(&g_ticket, 0u);
    }
}

// ---------------- launch ----------------
extern "C" void kernel_launch(void* const* d_in, const int* in_sizes, int n_in,
                              void* d_out, int out_size)
{
    const float* x  = (const float*)d_in[0];   // [8,32,32,32,32] f32
    const float* Wc = (const float*)d_in[1];   // [256,32] f32
    float* out = (float*)d_out;

    float* loss_ptr = out;                      // 1 element
    float* outq     = out + 1;                  // 8388608 elements
    float* enc      = out + 1 + OUT_Q_ELEMS;    // 67108864 elements

    cudaFuncSetAttribute(som_mma_kernel,
                         cudaFuncAttributeMaxDynamicSharedMemorySize, SMEM_BYTES);
    som_mma_kernel<<<GRID, 512, SMEM_BYTES>>>(x, Wc, outq, enc, loss_ptr);
}